// round 14
// baseline (speedup 1.0000x reference)
#include <cuda_runtime.h>

// Batched 12-qubit state-vector simulator, sweep-fused, rot-CRX merged,
// DUAL-STATE: one CTA simulates TWO batch elements (independent SMEM states,
// scalar math). Each sweep processes both states back-to-back -> two
// independent dependency chains per thread (ILP latency hiding), one barrier
// per sweep serves both elements.

#define NQ     12
#define DIM    (1 << NQ)          // 4096
#define NPARAM (NQ * 4 * 5)       // 240
#define NTRIG  (NPARAM + NQ)      // 252
#define NT     256
#define NW     (NT / 32)
#define LAYF   192                // floats per layer in fused-matrix table

// ---------------- complex helpers (for matrix precompute) ----------------
struct C2 { float r, i; };
__device__ __forceinline__ C2 cmul(C2 a, C2 b) { return { a.r*b.r - a.i*b.i, a.r*b.i + a.i*b.r }; }
__device__ __forceinline__ C2 cadd(C2 a, C2 b) { return { a.r + b.r, a.i + b.i }; }
struct M2 { C2 a, b, c, d; };
__device__ __forceinline__ M2 mmul(const M2& x, const M2& y) {
    M2 r;
    r.a = cadd(cmul(x.a, y.a), cmul(x.b, y.c));
    r.b = cadd(cmul(x.a, y.b), cmul(x.b, y.d));
    r.c = cadd(cmul(x.c, y.a), cmul(x.d, y.c));
    r.d = cadd(cmul(x.c, y.b), cmul(x.d, y.d));
    return r;
}

struct M2F { float ar, ai, br, bi, cr, ci, dr, di; };

__device__ __forceinline__ M2F ldmat(const float* p) {
    float4 a = *reinterpret_cast<const float4*>(p);
    float4 b = *reinterpret_cast<const float4*>(p + 4);
    return { a.x, a.y, a.z, a.w, b.x, b.y, b.z, b.w };
}

// XOR swizzle: conflict-free (per half-warp) for every circular 4-bit group.
__device__ __forceinline__ int physof(int i) { return i ^ ((i >> 4) & 15) ^ ((i >> 8) & 15); }

// Deposit 8 bits of t into the 12-bit positions NOT in MASK.
template<int MASK>
__device__ __forceinline__ int pdep8(int t) {
    int base = 0;
#pragma unroll
    for (int p = 0; p < 12; p++) {
        if (!((MASK >> p) & 1)) { base |= (t & 1) << p; t >>= 1; }
    }
    return base;
}

// Single complex butterfly on (m, j) with matrix g.
__device__ __forceinline__ void btf1(float2 v[16], int m, int j, const M2F& g) {
    float x0 = v[m].x, y0 = v[m].y, x1 = v[j].x, y1 = v[j].y;
    v[m].x = g.ar*x0 - g.ai*y0 + g.br*x1 - g.bi*y1;
    v[m].y = g.ar*y0 + g.ai*x0 + g.br*y1 + g.bi*x1;
    v[j].x = g.cr*x0 - g.ci*y0 + g.dr*x1 - g.di*y1;
    v[j].y = g.cr*y0 + g.ci*x0 + g.dr*y1 + g.di*x1;
}

// Generic complex 2x2 gate on local bit LB of the 16-amp register block.
template<int LB>
__device__ __forceinline__ void rot16(float2 v[16], M2F g) {
#pragma unroll
    for (int m = 0; m < 16; m++)
        if (!((m >> LB) & 1)) btf1(v, m, m | (1 << LB), g);
}

// Controlled general 2x2: ctrl local bit CB, target local bit TB.
// mp -> M0 (8 floats, ctrl=0), mp+8 -> M1 (ctrl=1).
template<int CB, int TB>
__device__ __forceinline__ void cgate16(float2 v[16], const float* mp) {
    M2F g = ldmat(mp);
#pragma unroll
    for (int m = 0; m < 16; m++)
        if (!((m >> TB) & 1) && !((m >> CB) & 1)) btf1(v, m, m | (1 << TB), g);
    g = ldmat(mp + 8);
#pragma unroll
    for (int m = 0; m < 16; m++)
        if (!((m >> TB) & 1) && ((m >> CB) & 1)) btf1(v, m, m | (1 << TB), g);
}

// CRX: control local bit CB, target local bit TB. c=cos(th/2), s=sin(th/2).
template<int CB, int TB>
__device__ __forceinline__ void crx16(float2 v[16], float c, float s) {
#pragma unroll
    for (int m = 0; m < 16; m++) {
        if (((m >> CB) & 1) && !((m >> TB) & 1)) {
            int j = m | (1 << TB);
            float x0 = v[m].x, y0 = v[m].y, x1 = v[j].x, y1 = v[j].y;
            v[m].x = c*x0 + s*y1;  v[m].y = c*y0 - s*x1;
            v[j].x = c*x1 + s*y0;  v[j].y = c*y1 - s*x0;
        }
    }
}

// Register-block load/store shared by all sweeps.
template<int B0, int B1, int B2, int B3>
__device__ __forceinline__ int blk_load(const float2* st, int tid, float2 v[16]) {
    constexpr int MASK = (1 << B0) | (1 << B1) | (1 << B2) | (1 << B3);
    const int pbase = physof(pdep8<MASK>(tid));
#pragma unroll
    for (int m = 0; m < 16; m++) {
        int place = ((m & 1) << B0) | (((m >> 1) & 1) << B1)
                  | (((m >> 2) & 1) << B2) | (((m >> 3) & 1) << B3);
        v[m] = st[pbase ^ physof(place)];
    }
    return pbase;
}
template<int B0, int B1, int B2, int B3>
__device__ __forceinline__ void blk_store(float2* st, int pbase, const float2 v[16]) {
#pragma unroll
    for (int m = 0; m < 16; m++) {
        int place = ((m & 1) << B0) | (((m >> 1) & 1) << B1)
                  | (((m >> 2) & 1) << B2) | (((m >> 3) & 1) << B3);
        st[pbase ^ physof(place)] = v[m];
    }
}

// Gate sequence of a forward sweep on one register block.
template<int ROT0, int NCG>
__device__ __forceinline__ void fwd_gates(float2 v[16], const float* rot0p,
                                          const float* edgep, float cc, float cs)
{
    if (ROT0) rot16<0>(v, ldmat(rot0p));
    cgate16<0, 1>(v, edgep);
    cgate16<1, 2>(v, edgep + 16);
    if (NCG >= 3) cgate16<2, 3>(v, edgep + 32);
    else          crx16<2, 3>(v, cc, cs);
}

// Dual-state forward sweep.
template<int B0, int B1, int B2, int B3, int ROT0, int NCG>
__device__ __forceinline__ void sweepF2(float2* stA, float2* stB, int tid,
                                        const float* rA, const float* eA,
                                        const float* rB, const float* eB,
                                        float ccA, float csA, float ccB, float csB)
{
    float2 vA[16], vB[16];
    int pbase = blk_load<B0, B1, B2, B3>(stA, tid, vA);
    blk_load<B0, B1, B2, B3>(stB, tid, vB);
    fwd_gates<ROT0, NCG>(vA, rA, eA, ccA, csA);
    fwd_gates<ROT0, NCG>(vB, rB, eB, ccB, csB);
    blk_store<B0, B1, B2, B3>(stA, pbase, vA);
    blk_store<B0, B1, B2, B3>(stB, pbase, vB);
}

// Dual-state backward sweep: 3 plain CRX edges per state.
template<int B0, int B1, int B2, int B3>
__device__ __forceinline__ void sweepB2(float2* stA, float2* stB, int tid,
                                        const float* pcA, const float* psA,
                                        const float* pcB, const float* psB, int pb)
{
    float2 vA[16], vB[16];
    int pbase = blk_load<B0, B1, B2, B3>(stA, tid, vA);
    blk_load<B0, B1, B2, B3>(stB, tid, vB);
    crx16<0, 1>(vA, pcA[pb+0], psA[pb+0]);
    crx16<1, 2>(vA, pcA[pb+1], psA[pb+1]);
    crx16<2, 3>(vA, pcA[pb+2], psA[pb+2]);
    crx16<0, 1>(vB, pcB[pb+0], psB[pb+0]);
    crx16<1, 2>(vB, pcB[pb+1], psB[pb+1]);
    crx16<2, 3>(vB, pcB[pb+2], psB[pb+2]);
    blk_store<B0, B1, B2, B3>(stA, pbase, vA);
    blk_store<B0, B1, B2, B3>(stB, pbase, vB);
}

// Expectation contributions for the 4 local bits of one group (single state).
template<int B0, int B1, int B2, int B3>
__device__ __forceinline__ void expect4(const float2* st, int tid, float* sred)
{
    float2 v[16];
    blk_load<B0, B1, B2, B3>(st, tid, v);
    const int bits[4] = { B0, B1, B2, B3 };
#pragma unroll
    for (int k = 0; k < 4; k++) {
        float xr = 0.f, xi = 0.f, zz = 0.f;
#pragma unroll
        for (int m = 0; m < 16; m++) {
            if (!((m >> k) & 1)) {
                float2 a = v[m], c = v[m | (1 << k)];
                xr += a.x * c.x + a.y * c.y;
                xi += a.x * c.y - a.y * c.x;
                zz += a.x * a.x + a.y * a.y - c.x * c.x - c.y * c.y;
            }
        }
#pragma unroll
        for (int o = 16; o; o >>= 1) {
            xr += __shfl_down_sync(0xffffffffu, xr, o);
            xi += __shfl_down_sync(0xffffffffu, xi, o);
            zz += __shfl_down_sync(0xffffffffu, zz, o);
        }
        if ((tid & 31) == 0) {
            int q = 11 - bits[k];
            int w = tid >> 5;
            sred[(q * 3 + 0) * NW + w] = xr;
            sred[(q * 3 + 1) * NW + w] = xi;
            sred[(q * 3 + 2) * NW + w] = zz;
        }
    }
}

// Build fused matrices for one element into its smats table.
__device__ __forceinline__ void build_mats(const float* pc_, const float* ps_,
                                           float* smats_, int l, int k)
{
    int p = l * 60 + k * 3;
    float cx = pc_[p],     sx = ps_[p];
    float cy = pc_[p + 1], sy = ps_[p + 1];
    float cz = pc_[p + 2], sz = ps_[p + 2];
    M2 rx = { {cx, 0.f}, {0.f, -sx}, {0.f, -sx}, {cx, 0.f} };
    M2 ry = { {cy, 0.f}, {-sy, 0.f}, {sy, 0.f},  {cy, 0.f} };
    M2 rz = { {cz, -sz}, {0.f, 0.f}, {0.f, 0.f}, {cz, sz} };
    M2 mm = mmul(rz, mmul(ry, rx));
    if (l == 0) {
        float ce = pc_[NPARAM + k], se = ps_[NPARAM + k];
        M2 rye = { {ce, 0.f}, {-se, 0.f}, {se, 0.f}, {ce, 0.f} };
        mm = mmul(mm, rye);
    }
    float* base = smats_ + l * LAYF;
    if (k == 0) {
        float* o = base;
        o[0] = mm.a.r; o[1] = mm.a.i; o[2] = mm.b.r; o[3] = mm.b.i;
        o[4] = mm.c.r; o[5] = mm.c.i; o[6] = mm.d.r; o[7] = mm.d.i;
    } else {
        int e = k - 1;
        float* o = base + 8 + e * 16;
        o[0] = mm.a.r; o[1] = mm.a.i; o[2] = mm.b.r; o[3] = mm.b.i;
        o[4] = mm.c.r; o[5] = mm.c.i; o[6] = mm.d.r; o[7] = mm.d.i;
        int pe = l * 60 + 36 + e;
        float ec = pc_[pe], es = ps_[pe];
        M2 rxe = { {ec, 0.f}, {0.f, -es}, {0.f, -es}, {ec, 0.f} };
        M2 m1 = mmul(rxe, mm);
        float* o1 = o + 8;
        o1[0] = m1.a.r; o1[1] = m1.a.i; o1[2] = m1.b.r; o1[3] = m1.b.i;
        o1[4] = m1.c.r; o1[5] = m1.c.i; o1[6] = m1.d.r; o1[7] = m1.d.i;
    }
}

// Dynamic SMEM (bytes): stA(32K) stB(32K) smatsA/B(2*3072) pc/ps A/B(4*1008) sredA/B(2*1152)
#define SMEM_BYTES (DIM * 8 * 2 + 2 * 4 * LAYF * 4 + 4 * NTRIG * 4 + 2 * 36 * NW * 4)

__global__ void __launch_bounds__(NT, 2)
qsim_kernel(const float* __restrict__ params,
            const float* __restrict__ inputs,
            float* __restrict__ out, int B)
{
    extern __shared__ float2 dyn2[];
    float2* stA = dyn2;
    float2* stB = dyn2 + DIM;
    float*  fb  = reinterpret_cast<float*>(dyn2 + 2 * DIM);
    float* smatsA = fb;                    // 4*LAYF = 768
    float* smatsB = fb + 4 * LAYF;
    float* pcA = fb + 8 * LAYF;            // NTRIG each
    float* psA = pcA + NTRIG;
    float* pcB = psA + NTRIG;
    float* psB = pcB + NTRIG;
    float* sredA = psB + NTRIG;            // 36*NW each
    float* sredB = sredA + 36 * NW;

    const int tid = threadIdx.x;
    const int b   = blockIdx.x;
    const int e0  = 2 * b;
    const int e1  = (2 * b + 1 < B) ? (2 * b + 1) : (2 * b);

    // half-angle trig for both elements
    for (int t = tid; t < NTRIG; t += NT) {
        float thA = (t < NPARAM) ? params[(size_t)e0 * NPARAM + t]
                                 : inputs[(size_t)e0 * NQ + (t - NPARAM)];
        float thB = (t < NPARAM) ? params[(size_t)e1 * NPARAM + t]
                                 : inputs[(size_t)e1 * NQ + (t - NPARAM)];
        float s, c;
        sincosf(0.5f * thA, &s, &c);  pcA[t] = c; psA[t] = s;
        sincosf(0.5f * thB, &s, &c);  pcB[t] = c; psB[t] = s;
    }
    for (int i = tid; i < DIM; i += NT) {
        stA[i] = make_float2(0.f, 0.f);
        stB[i] = make_float2(0.f, 0.f);
    }
    __syncthreads();

    // Matrices: thread -> (element lane, layer, chain position k).
    if (tid < 96) {
        int e = tid & 1, idx = tid >> 1;   // idx in [0,48)
        int l = idx / 12, k = idx % 12;
        if (e == 0) build_mats(pcA, psA, smatsA, l, k);
        else        build_mats(pcB, psB, smatsB, l, k);
    }
    if (tid == 0) {
        stA[0] = make_float2(1.f, 0.f);    // physof(0) == 0
        stB[0] = make_float2(1.f, 0.f);
    }
    __syncthreads();

    // Qubit q lives on bit 11-q. Forward ring CRX(q,q+1); backward CRX(q,q-1).
#pragma unroll 1
    for (int l = 0; l < 4; l++) {
        const float* SA = smatsA + l * LAYF;
        const float* SB = smatsB + l * LAYF;
        const int pf = l * 60 + 36;
        const int pb = l * 60 + 48;

        // qubits 0-3: rot0 + merged edges 0,1,2
        sweepF2<11,10,9,8, 1,3>(stA, stB, tid, SA, SA + 8, SB, SB + 8,
                                0.f, 0.f, 0.f, 0.f);
        __syncthreads();
        // qubits 3-6: merged edges 3,4,5
        sweepF2<8,7,6,5, 0,3>(stA, stB, tid, SA, SA + 8 + 3*16, SB, SB + 8 + 3*16,
                              0.f, 0.f, 0.f, 0.f);
        __syncthreads();
        // qubits 6-9: merged edges 6,7,8
        sweepF2<5,4,3,2, 0,3>(stA, stB, tid, SA, SA + 8 + 6*16, SB, SB + 8 + 6*16,
                              0.f, 0.f, 0.f, 0.f);
        __syncthreads();
        // qubits 9,10,11,0: merged edges 9,10 + plain CRX(11,0)
        sweepF2<2,1,0,11, 0,2>(stA, stB, tid, SA, SA + 8 + 9*16, SB, SB + 8 + 9*16,
                               pcA[pf+11], psA[pf+11], pcB[pf+11], psB[pf+11]);
        __syncthreads();
        // backward ring: 4 sweeps of 3 CRX edges each
        sweepB2<0,1,2,3>(stA, stB, tid, pcA, psA, pcB, psB, pb + 0);
        __syncthreads();
        sweepB2<3,4,5,6>(stA, stB, tid, pcA, psA, pcB, psB, pb + 3);
        __syncthreads();
        sweepB2<6,7,8,9>(stA, stB, tid, pcA, psA, pcB, psB, pb + 6);
        __syncthreads();
        sweepB2<9,10,11,0>(stA, stB, tid, pcA, psA, pcB, psB, pb + 9);
        __syncthreads();
    }

    // Expectation values, 3 register passes per state covering all 12 bits.
    expect4<0, 1, 2, 3>(stA, tid, sredA);
    expect4<0, 1, 2, 3>(stB, tid, sredB);
    expect4<4, 5, 6, 7>(stA, tid, sredA);
    expect4<4, 5, 6, 7>(stB, tid, sredB);
    expect4<8, 9, 10, 11>(stA, tid, sredA);
    expect4<8, 9, 10, 11>(stB, tid, sredB);
    __syncthreads();

    if (tid < 36) {
        float aA = 0.f, aB = 0.f;
#pragma unroll
        for (int w = 0; w < NW; w++) {
            aA += sredA[tid * NW + w];
            aB += sredB[tid * NW + w];
        }
        int q = tid / 3, comp = tid - q * 3;
        float sc = (comp == 2) ? 1.f : 2.f;
        out[(size_t)e0 * 36 + comp * 12 + q] = sc * aA;
        if (2 * b + 1 < B)
            out[(size_t)(2 * b + 1) * 36 + comp * 12 + q] = sc * aB;
    }
}

extern "C" void kernel_launch(void* const* d_in, const int* in_sizes, int n_in,
                              void* d_out, int out_size)
{
    const float* params = (const float*)d_in[0];
    const float* inputs = (const float*)d_in[1];
    int sz_p = in_sizes[0], sz_i = in_sizes[1];
    if (n_in >= 2 && sz_p < sz_i) {  // robust to input ordering
        const float* t = params; params = inputs; inputs = t;
        int ts = sz_p; sz_p = sz_i; sz_i = ts;
    }
    int B = sz_p / NPARAM;  // 1024
    cudaFuncSetAttribute(qsim_kernel, cudaFuncAttributeMaxDynamicSharedMemorySize,
                         SMEM_BYTES);
    int grid = (B + 1) / 2;
    qsim_kernel<<<grid, NT, SMEM_BYTES>>>(params, inputs, (float*)d_out, B);
}